// round 11
// baseline (speedup 1.0000x reference)
#include <cuda_runtime.h>
#include <math.h>

#define BATCH 2
#define NC 8
#define NE 16
#define NSEG 17
#define DD 64
#define HH 128
#define WW 128
#define NVOX (DD*HH*WW)      /* 1048576 per batch */
#define NTOT (BATCH*NVOX)

#define PREP_BLOCKS 592
#define NCH_PREP 8192        /* 256 voxels/chunk, both batches (b = ch>>12) */
#define SEG_B0 194           /* seg blocks per batch */
#define CE_B0 102            /* ce blocks per batch */
#define FUSED_BLOCKS (2*SEG_B0 + 2*CE_B0)   /* 592 */
#define NCH_SEG 2048         /* per batch; chunk = 16 pp units = 512 voxels */
#define NCH_CE 512           /* per batch; chunk = 1024 float2 units */
#define PULL_BLOCKS 296
#define NCH_PULL 2048        /* chunk = 256 int4 units = 1024 voxels; b = ch>>10 */

// ---------------- scratch (device globals; zero-initialized at load) --------
__device__ int   g_packed[NTOT];       // label | (boundary ? sign bit : 0)
__device__ float g_nll;
__device__ float g_cardp[BATCH][NC];
__device__ float g_inter[BATCH][NC];
__device__ float g_hist[BATCH][NC];
__device__ float g_cnt[BATCH][NSEG];
__device__ float g_bcnt[BATCH][NSEG];
__device__ float g_cnum[BATCH][NSEG][NE];
__device__ float g_pull[BATCH][NSEG];
// work-stealing counters: 0 prep, 1-2 seg(b), 3-4 ce(b), 5 pull, 6 done
__device__ int   g_ctrs[8];

__device__ __forceinline__ unsigned cvt_bf16x2(float x, float y) {
    unsigned d;
    asm("cvt.rn.bf16x2.f32 %0, %1, %2;" : "=r"(d) : "f"(y), "f"(x));
    return d;
}
__device__ __forceinline__ unsigned hb(int p, int n) {
    int l = p & 0x7fffffff;
    unsigned w = (p < 0) ? 0x4120u : 0x3F80u;   // bf16 10.0 : 1.0
    return (l == n) ? w : 0u;
}

// ------ prep: boundary + pack + histograms (dynamic chunks) ------
__global__ void __launch_bounds__(256) prep_kernel(const int* __restrict__ lab,
                                                   const int* __restrict__ cls) {
    __shared__ float s_cnt[BATCH][NSEG], s_bcnt[BATCH][NSEG], s_hist[BATCH][NC];
    __shared__ int s_chunk;
    for (int j = threadIdx.x; j < BATCH*NSEG; j += 256) {
        (&s_cnt[0][0])[j] = 0.f; (&s_bcnt[0][0])[j] = 0.f;
    }
    if (threadIdx.x < BATCH*NC) (&s_hist[0][0])[threadIdx.x] = 0.f;
    __syncthreads();

    while (true) {
        if (threadIdx.x == 0) s_chunk = atomicAdd(&g_ctrs[0], 1);
        __syncthreads();
        int ch = s_chunk;
        if (ch >= NCH_PREP) break;
        int b = ch >> 12;
        int v = ((ch & 4095) << 8) + threadIdx.x;
        int d = v >> 14;
        int r = v & 16383;
        int h = r >> 7;
        int x = r & 127;
        const int* Lb = lab + (size_t)b * NVOX;
        int c0 = Lb[v];
        bool diff = false;
#pragma unroll
        for (int dd = -1; dd <= 1; dd++) {
            int zd = min(max(d + dd, 0), DD - 1);
#pragma unroll
            for (int dh = -1; dh <= 1; dh++) {
                int zh = min(max(h + dh, 0), HH - 1);
#pragma unroll
                for (int dx = -1; dx <= 1; dx++) {
                    int zx = min(max(x + dx, 0), WW - 1);
                    diff |= (Lb[(zd << 14) + (zh << 7) + zx] != c0);
                }
            }
        }
        g_packed[(size_t)b * NVOX + v] = c0 | (diff ? 0x80000000 : 0);
        atomicAdd(&s_cnt[b][c0], 1.f);
        if (diff) atomicAdd(&s_bcnt[b][c0], 1.f);
        atomicAdd(&s_hist[b][cls[(size_t)b * NVOX + v]], 1.f);
        __syncthreads();
    }
    __syncthreads();
    for (int j = threadIdx.x; j < BATCH*NSEG; j += 256) {
        int b = j / NSEG, k = j % NSEG;
        if (s_cnt[b][k]  != 0.f) atomicAdd(&g_cnt[b][k],  s_cnt[b][k]);
        if (s_bcnt[b][k] != 0.f) atomicAdd(&g_bcnt[b][k], s_bcnt[b][k]);
    }
    if (threadIdx.x < BATCH*NC) {
        int b = threadIdx.x / NC, c = threadIdx.x % NC;
        if (s_hist[b][c] != 0.f) atomicAdd(&g_hist[b][c], s_hist[b][c]);
    }
}

// ------- segstat body: one-hot GEMM via mma, dynamic chunks -------
__device__ __forceinline__ void segstat_body(const float* __restrict__ embed, int b) {
    const float* eb = embed + (size_t)b * NE * NVOX;
    const int*   pb = g_packed + (size_t)b * NVOX;

    int lane = threadIdx.x & 31;
    int warp = threadIdx.x >> 5;
    int t  = lane & 3;
    int gq = lane >> 2;

    float d[3][4];
#pragma unroll
    for (int f = 0; f < 3; f++)
#pragma unroll
        for (int r = 0; r < 4; r++) d[f][r] = 0.f;

    const float* r0base = eb + (size_t)gq * NVOX;
    const float* r1base = eb + (size_t)(gq + 8) * NVOX;

    __shared__ int s_chunk;
    while (true) {
        if (threadIdx.x == 0) s_chunk = atomicAdd(&g_ctrs[1 + b], 1);
        __syncthreads();
        int ch = s_chunk;
        if (ch >= NCH_SEG) break;
#pragma unroll
        for (int it = 0; it < 2; it++) {
            int pp = ch * 16 + warp * 2 + it;
            int base0 = pp * 32 + 4 * t;
            int base1 = base0 + 16;
            int4   pA  = *(const int4*)(pb + base0);
            int4   pB  = *(const int4*)(pb + base1);
            float4 a0A = *(const float4*)(r0base + base0);
            float4 a1A = *(const float4*)(r1base + base0);
            float4 a0B = *(const float4*)(r0base + base1);
            float4 a1B = *(const float4*)(r1base + base1);

            unsigned A0 = cvt_bf16x2(a0A.x, a0A.y);
            unsigned A1 = cvt_bf16x2(a1A.x, a1A.y);
            unsigned A2 = cvt_bf16x2(a0A.z, a0A.w);
            unsigned A3 = cvt_bf16x2(a1A.z, a1A.w);
#pragma unroll
            for (int f = 0; f < 3; f++) {
                int n = gq + 8*f;
                unsigned B0 = hb(pA.x, n) | (hb(pA.y, n) << 16);
                unsigned B1 = hb(pA.z, n) | (hb(pA.w, n) << 16);
                asm volatile(
                    "mma.sync.aligned.m16n8k16.row.col.f32.bf16.bf16.f32 "
                    "{%0,%1,%2,%3}, {%4,%5,%6,%7}, {%8,%9}, {%0,%1,%2,%3};"
                    : "+f"(d[f][0]), "+f"(d[f][1]), "+f"(d[f][2]), "+f"(d[f][3])
                    : "r"(A0), "r"(A1), "r"(A2), "r"(A3), "r"(B0), "r"(B1));
            }
            unsigned C0 = cvt_bf16x2(a0B.x, a0B.y);
            unsigned C1 = cvt_bf16x2(a1B.x, a1B.y);
            unsigned C2 = cvt_bf16x2(a0B.z, a0B.w);
            unsigned C3 = cvt_bf16x2(a1B.z, a1B.w);
#pragma unroll
            for (int f = 0; f < 3; f++) {
                int n = gq + 8*f;
                unsigned B0 = hb(pB.x, n) | (hb(pB.y, n) << 16);
                unsigned B1 = hb(pB.z, n) | (hb(pB.w, n) << 16);
                asm volatile(
                    "mma.sync.aligned.m16n8k16.row.col.f32.bf16.bf16.f32 "
                    "{%0,%1,%2,%3}, {%4,%5,%6,%7}, {%8,%9}, {%0,%1,%2,%3};"
                    : "+f"(d[f][0]), "+f"(d[f][1]), "+f"(d[f][2]), "+f"(d[f][3])
                    : "r"(C0), "r"(C1), "r"(C2), "r"(C3), "r"(B0), "r"(B1));
            }
        }
        __syncthreads();
    }

    __shared__ float s_cnum[NSEG][NE];
    for (int j = threadIdx.x; j < NSEG*NE; j += blockDim.x) (&s_cnum[0][0])[j] = 0.f;
    __syncthreads();
#pragma unroll
    for (int f = 0; f < 3; f++) {
        int n0 = 8*f + 2*t;
        if (n0 < NSEG) {
            atomicAdd(&s_cnum[n0][gq],     d[f][0]);
            atomicAdd(&s_cnum[n0][gq + 8], d[f][2]);
        }
        if (n0 + 1 < NSEG) {
            atomicAdd(&s_cnum[n0+1][gq],     d[f][1]);
            atomicAdd(&s_cnum[n0+1][gq + 8], d[f][3]);
        }
    }
    __syncthreads();
    for (int j = threadIdx.x; j < NSEG*NE; j += blockDim.x) {
        float v = (&s_cnum[0][0])[j];
        if (v != 0.f) atomicAdd(&g_cnum[b][0][0] + j, v);
    }
}

// ------- ce_dice body: float2, dynamic chunks -------
__device__ __forceinline__ void ce_body(const float* __restrict__ logits,
                                        const int* __restrict__ cls, int b) {
    const float2* lb = (const float2*)(logits + (size_t)b * NC * NVOX);
    const int2*   cb = (const int2*)(cls + (size_t)b * NVOX);

    float r_nll = 0.f;
    float r_cardp[NC], r_inter[NC];
#pragma unroll
    for (int c = 0; c < NC; c++) { r_cardp[c]=0.f; r_inter[c]=0.f; }

    __shared__ int s_chunk;
    while (true) {
        if (threadIdx.x == 0) s_chunk = atomicAdd(&g_ctrs[3 + b], 1);
        __syncthreads();
        int ch = s_chunk;
        if (ch >= NCH_CE) break;
        int base = ch * 1024;
#pragma unroll
        for (int it = 0; it < 4; it++) {
            int i = base + it * 256 + threadIdx.x;
            int2 t2 = cb[i];
            float2 x2[NC];
#pragma unroll
            for (int c = 0; c < NC; c++) x2[c] = lb[(size_t)c * (NVOX/2) + i];
#pragma unroll
            for (int j = 0; j < 2; j++) {
                float xv[NC];
#pragma unroll
                for (int c = 0; c < NC; c++) xv[c] = j ? x2[c].y : x2[c].x;
                int t = j ? t2.y : t2.x;

                float m = xv[0];
#pragma unroll
                for (int c = 1; c < NC; c++) m = fmaxf(m, xv[c]);
                float ex[NC]; float s = 0.f;
#pragma unroll
                for (int c = 0; c < NC; c++) { ex[c] = __expf(xv[c] - m); s += ex[c]; }
                float inv = 1.0f / s;
                float lse = m + __logf(s);
#pragma unroll
                for (int c = 0; c < NC; c++) {
                    float p = ex[c] * inv;
                    r_cardp[c] += p;
                    if (t == c) {
                        r_inter[c] += p;
                        r_nll += lse - xv[c];
                    }
                }
            }
        }
        __syncthreads();
    }

    __shared__ float s_acc[17];
    if (threadIdx.x < 17) s_acc[threadIdx.x] = 0.f;
    __syncthreads();
    float vals[17];
    vals[0] = r_nll;
#pragma unroll
    for (int c = 0; c < NC; c++) { vals[1+c]=r_cardp[c]; vals[9+c]=r_inter[c]; }
#pragma unroll
    for (int k = 0; k < 17; k++) {
        float v = vals[k];
#pragma unroll
        for (int o = 16; o; o >>= 1) v += __shfl_xor_sync(0xffffffffu, v, o);
        if ((threadIdx.x & 31) == 0) atomicAdd(&s_acc[k], v);
    }
    __syncthreads();
    int t = threadIdx.x;
    if (t == 0)       atomicAdd(&g_nll, s_acc[0]);
    else if (t < 9)   atomicAdd(&g_cardp[b][t-1], s_acc[t]);
    else if (t < 17)  atomicAdd(&g_inter[b][t-9], s_acc[t]);
}

// ------- fused main pass -------
__global__ void __launch_bounds__(256, 4) fused_main(const float* __restrict__ embed,
                                                     const float* __restrict__ logits,
                                                     const int* __restrict__ cls) {
    int bx = blockIdx.x;
    if (bx < 2*SEG_B0)      segstat_body(embed, bx < SEG_B0 ? 0 : 1);
    else                    ce_body(logits, cls, (bx - 2*SEG_B0) < CE_B0 ? 0 : 1);
}

// ---------------- pull (dynamic chunks, both batches) + final fold ----------
__global__ void __launch_bounds__(256, 2) pull_kernel(const float* __restrict__ embed,
                                                      float* __restrict__ out) {
    __shared__ float sc[BATCH][NSEG][NE + 1];
    __shared__ float s_pull[BATCH][NSEG];
    __shared__ int s_chunk;
    __shared__ int s_isLast;
    for (int j = threadIdx.x; j < BATCH*NSEG*NE; j += 256) {
        int b = j / (NSEG*NE);
        int k = (j / NE) % NSEG;
        int c = j % NE;
        float wsum = g_cnt[b][k] + 9.0f * g_bcnt[b][k];
        sc[b][k][c] = g_cnum[b][k][c] / (wsum + 1e-8f);
    }
    for (int j = threadIdx.x; j < BATCH*NSEG; j += 256) (&s_pull[0][0])[j] = 0.f;
    __syncthreads();

    while (true) {
        if (threadIdx.x == 0) s_chunk = atomicAdd(&g_ctrs[5], 1);
        __syncthreads();
        int ch = s_chunk;
        if (ch >= NCH_PULL) break;
        int b = ch >> 10;
        const float4* eb = (const float4*)(embed + (size_t)b * NE * NVOX);
        const int4*   pb = (const int4*)(g_packed + (size_t)b * NVOX);
        int i = ((ch & 1023) << 8) + threadIdx.x;

        int4 p4 = pb[i];
        float4 e4[NE];
#pragma unroll
        for (int c = 0; c < NE; c++)
            e4[c] = eb[(size_t)c * (NVOX/4) + i];

        int   lv[4]; float wv[4]; float ds[4];
#pragma unroll
        for (int j = 0; j < 4; j++) {
            int p = (j==0) ? p4.x : (j==1) ? p4.y : (j==2) ? p4.z : p4.w;
            lv[j] = p & 0x7fffffff;
            wv[j] = (p < 0) ? 10.f : 1.f;
            ds[j] = 0.f;
        }
#pragma unroll
        for (int c = 0; c < NE; c++) {
#pragma unroll
            for (int j = 0; j < 4; j++) {
                float ev = (j==0) ? e4[c].x : (j==1) ? e4[c].y : (j==2) ? e4[c].z : e4[c].w;
                float dv = ev - sc[b][lv[j]][c];
                ds[j] += dv * dv;
            }
        }
#pragma unroll
        for (int j = 0; j < 4; j++) {
            float dist = sqrtf(ds[j]);
            float tt = fmaxf(dist - 0.5f, 0.f);
            atomicAdd(&s_pull[b][lv[j]], tt * tt * wv[j]);
        }
        __syncthreads();
    }
    __syncthreads();
    for (int j = threadIdx.x; j < BATCH*NSEG; j += 256) {
        int b = j / NSEG, k = j % NSEG;
        if (s_pull[b][k] != 0.f) atomicAdd(&g_pull[b][k], s_pull[b][k]);
    }

    // last-block final combine + cleanup
    __threadfence();
    __syncthreads();
    if (threadIdx.x == 0)
        s_isLast = (atomicAdd(&g_ctrs[6], 1) == PULL_BLOCKS - 1) ? 1 : 0;
    __syncthreads();
    if (!s_isLast) return;

    __shared__ float s_lp[BATCH], s_push[BATCH], s_norm[BATCH], s_val[BATCH];
    int lane = threadIdx.x & 31;
    int warp = threadIdx.x >> 5;
    if (warp < BATCH) {
        int b = warp;
        int pres_lane = (lane >= 1 && lane < NSEG) ? (g_cnt[b][lane] > 0.f ? 1 : 0) : 0;
        unsigned mask = __ballot_sync(0xffffffffu, pres_lane);
        float np = (float)__popc(mask);

        float lp = pres_lane ? g_pull[b][lane] / fmaxf(g_cnt[b][lane], 1.f) : 0.f;
#pragma unroll
        for (int o = 16; o; o >>= 1) lp += __shfl_xor_sync(0xffffffffu, lp, o);

        float pacc = 0.f;
        for (int pp = lane; pp < 120; pp += 32) {
            int i = 1, rem = pp;
            while (rem >= (NSEG - 1) - i) { rem -= (NSEG - 1) - i; i++; }
            int jj = i + 1 + rem;
            float dsq = 0.f;
#pragma unroll
            for (int c = 0; c < NE; c++) { float dv = sc[b][i][c] - sc[b][jj][c]; dsq += dv * dv; }
            float pw = sqrtf(dsq);
            float tt = fmaxf(3.0f - pw, 0.f);
            if (((mask >> i) & 1) && ((mask >> jj) & 1)) pacc += tt * tt;
        }
#pragma unroll
        for (int o = 16; o; o >>= 1) pacc += __shfl_xor_sync(0xffffffffu, pacc, o);

        float nacc = 0.f;
        if (pres_lane) {
            float dsq = 0.f;
#pragma unroll
            for (int c = 0; c < NE; c++) dsq += sc[b][lane][c] * sc[b][lane][c];
            nacc = sqrtf(dsq);
        }
#pragma unroll
        for (int o = 16; o; o >>= 1) nacc += __shfl_xor_sync(0xffffffffu, nacc, o);

        if (lane == 0) {
            float npairs = np * (np - 1.f) * 0.5f;
            s_lp[b]   = lp;
            s_push[b] = (npairs > 0.f) ? pacc / fmaxf(npairs, 1.f) : 0.f;
            s_norm[b] = (np > 0.f)     ? nacc / fmaxf(np, 1.f)     : 0.f;
            s_val[b]  = (np > 0.f) ? 1.f : 0.f;
        }
    }
    __syncthreads();

    if (threadIdx.x == 0) {
        float lp_sum = 0.f, push_sum = 0.f, norm_sum = 0.f, val_sum = 0.f;
        for (int b = 0; b < BATCH; b++) {
            lp_sum += s_lp[b]; push_sum += s_push[b];
            norm_sum += s_norm[b]; val_sum += s_val[b];
        }
        float Nf = (float)NTOT;
        float ce = g_nll / Nf;
        float dsum = 0.f;
        for (int b = 0; b < BATCH; b++)
            for (int c = 0; c < NC; c++)
                dsum += (2.0f * g_inter[b][c] + 1e-5f) /
                        (g_cardp[b][c] + g_hist[b][c] + 1e-5f);
        float dice = 1.0f - dsum / (float)(BATCH * NC);

        float ins = (lp_sum + push_sum + 0.001f * norm_sum) / fmaxf(val_sum, 1.f);
        float sem = ce + dice;
        out[0] = sem + ins;
        out[1] = sem;
        out[2] = ce;
        out[3] = dice;
        out[4] = ins;
    }
    __syncthreads();

    // reset accumulators + counters for the next graph replay
    for (int j = threadIdx.x; j < BATCH*NC; j += 256) {
        (&g_cardp[0][0])[j] = 0.f;
        (&g_inter[0][0])[j] = 0.f;
        (&g_hist[0][0])[j]  = 0.f;
    }
    for (int j = threadIdx.x; j < BATCH*NSEG; j += 256) {
        (&g_cnt[0][0])[j]  = 0.f;
        (&g_bcnt[0][0])[j] = 0.f;
        (&g_pull[0][0])[j] = 0.f;
    }
    for (int j = threadIdx.x; j < BATCH*NSEG*NE; j += 256)
        (&g_cnum[0][0][0])[j] = 0.f;
    if (threadIdx.x < 8) g_ctrs[threadIdx.x] = 0;
    if (threadIdx.x == 0) g_nll = 0.f;
}

// ---------------- launch ----------------
extern "C" void kernel_launch(void* const* d_in, const int* in_sizes, int n_in,
                              void* d_out, int out_size) {
    const float* sem = (const float*)d_in[0];
    const float* emb = (const float*)d_in[1];
    const int*   cls = (const int*)d_in[2];
    const int*   lab = (const int*)d_in[3];
    float* out = (float*)d_out;

    prep_kernel<<<PREP_BLOCKS, 256>>>(lab, cls);
    fused_main<<<FUSED_BLOCKS, 256>>>(emb, sem, cls);
    pull_kernel<<<PULL_BLOCKS, 256>>>(emb, out);
}

// round 15
// speedup vs baseline: 1.1823x; 1.1823x over previous
#include <cuda_runtime.h>
#include <math.h>

#define BATCH 2
#define NC 8
#define NE 16
#define NSEG 17
#define DD 64
#define HH 128
#define WW 128
#define NVOX (DD*HH*WW)      /* 1048576 per batch */
#define NTOT (BATCH*NVOX)

#define SEG_X 296            /* segstat blocks per batch in fused kernel */
#define CE_X  296            /* ce_dice blocks per batch in fused kernel */
#define PULL_X 592
#define PULL_TOTAL (PULL_X * BATCH)

// ---------------- scratch (device globals; zero-initialized at load) --------
__device__ int   g_packed[NTOT];       // label | (boundary ? sign bit : 0)
__device__ float g_nll;
__device__ float g_cardp[BATCH][NC];
__device__ float g_inter[BATCH][NC];
__device__ float g_hist[BATCH][NC];    // class counts (= cardg)
__device__ float g_cnt[BATCH][NSEG];
__device__ float g_bcnt[BATCH][NSEG];  // boundary counts per segment
__device__ float g_cnum[BATCH][NSEG][NE];
__device__ float g_pull[BATCH][NSEG];
__device__ int   g_done;

// pack two f32 into bf16x2: low = x, high = y
__device__ __forceinline__ unsigned cvt_bf16x2(float x, float y) {
    unsigned d;
    asm("cvt.rn.bf16x2.f32 %0, %1, %2;" : "=r"(d) : "f"(y), "f"(x));
    return d;
}

// one-hot half: (label(p)==n) ? bf16(w(p)) : 0
__device__ __forceinline__ unsigned hb(int p, int n) {
    int l = p & 0x7fffffff;
    unsigned w = (p < 0) ? 0x4120u : 0x3F80u;   // bf16 10.0 : 1.0
    return (l == n) ? w : 0u;
}

// ------ prep: boundary + pack + segment/class histograms ------
__global__ void __launch_bounds__(256) prep_kernel(const int* __restrict__ lab,
                                                   const int* __restrict__ cls) {
    __shared__ float s_cnt[NSEG], s_bcnt[NSEG], s_hist[NC];
    if (threadIdx.x < NSEG) { s_cnt[threadIdx.x] = 0.f; s_bcnt[threadIdx.x] = 0.f; }
    if (threadIdx.x < NC) s_hist[threadIdx.x] = 0.f;
    __syncthreads();

    int idx = blockIdx.x * blockDim.x + threadIdx.x;
    int b = idx >> 20;
    int v = idx & (NVOX - 1);
    int d = v >> 14;
    int r = v & 16383;
    int h = r >> 7;
    int x = r & 127;
    const int* Lb = lab + (size_t)b * NVOX;
    int c0 = Lb[v];
    bool diff = false;
#pragma unroll
    for (int dd = -1; dd <= 1; dd++) {
        int zd = min(max(d + dd, 0), DD - 1);
#pragma unroll
        for (int dh = -1; dh <= 1; dh++) {
            int zh = min(max(h + dh, 0), HH - 1);
#pragma unroll
            for (int dx = -1; dx <= 1; dx++) {
                int zx = min(max(x + dx, 0), WW - 1);
                diff |= (Lb[(zd << 14) + (zh << 7) + zx] != c0);
            }
        }
    }
    g_packed[idx] = c0 | (diff ? 0x80000000 : 0);

    atomicAdd(&s_cnt[c0], 1.f);
    if (diff) atomicAdd(&s_bcnt[c0], 1.f);
    int cl = cls[idx];
    atomicAdd(&s_hist[cl], 1.f);

    __syncthreads();
    if (threadIdx.x < NSEG) {
        if (s_cnt[threadIdx.x]  != 0.f) atomicAdd(&g_cnt[b][threadIdx.x],  s_cnt[threadIdx.x]);
        if (s_bcnt[threadIdx.x] != 0.f) atomicAdd(&g_bcnt[b][threadIdx.x], s_bcnt[threadIdx.x]);
    }
    if (threadIdx.x < NC && s_hist[threadIdx.x] != 0.f)
        atomicAdd(&g_hist[b][threadIdx.x], s_hist[threadIdx.x]);
}

// ------- segstat body: one-hot GEMM via mma.m16n8k16.bf16 -------
__device__ __forceinline__ void segstat_body(const float* __restrict__ embed,
                                             int b, int bx) {
    const float* eb = embed + (size_t)b * NE * NVOX;
    const int*   pb = g_packed + (size_t)b * NVOX;

    int lane = threadIdx.x & 31;
    int warp = threadIdx.x >> 5;
    int gwarp = bx * 8 + warp;
    int nwarps = SEG_X * 8;

    int t  = lane & 3;       // k-group
    int gq = lane >> 2;      // channel/segment group 0..7

    float d[3][4];
#pragma unroll
    for (int f = 0; f < 3; f++)
#pragma unroll
        for (int r = 0; r < 4; r++) d[f][r] = 0.f;

    const float* r0base = eb + (size_t)gq * NVOX;
    const float* r1base = eb + (size_t)(gq + 8) * NVOX;

    for (int pp = gwarp; pp < NVOX/32; pp += nwarps) {
        int base0 = pp * 32 + 4 * t;
        int base1 = base0 + 16;
        int4   pA  = *(const int4*)(pb + base0);
        int4   pB  = *(const int4*)(pb + base1);
        float4 a0A = *(const float4*)(r0base + base0);
        float4 a1A = *(const float4*)(r1base + base0);
        float4 a0B = *(const float4*)(r0base + base1);
        float4 a1B = *(const float4*)(r1base + base1);

        unsigned A0 = cvt_bf16x2(a0A.x, a0A.y);
        unsigned A1 = cvt_bf16x2(a1A.x, a1A.y);
        unsigned A2 = cvt_bf16x2(a0A.z, a0A.w);
        unsigned A3 = cvt_bf16x2(a1A.z, a1A.w);
#pragma unroll
        for (int f = 0; f < 3; f++) {
            int n = gq + 8*f;
            unsigned B0 = hb(pA.x, n) | (hb(pA.y, n) << 16);
            unsigned B1 = hb(pA.z, n) | (hb(pA.w, n) << 16);
            asm volatile(
                "mma.sync.aligned.m16n8k16.row.col.f32.bf16.bf16.f32 "
                "{%0,%1,%2,%3}, {%4,%5,%6,%7}, {%8,%9}, {%0,%1,%2,%3};"
                : "+f"(d[f][0]), "+f"(d[f][1]), "+f"(d[f][2]), "+f"(d[f][3])
                : "r"(A0), "r"(A1), "r"(A2), "r"(A3), "r"(B0), "r"(B1));
        }
        unsigned C0 = cvt_bf16x2(a0B.x, a0B.y);
        unsigned C1 = cvt_bf16x2(a1B.x, a1B.y);
        unsigned C2 = cvt_bf16x2(a0B.z, a0B.w);
        unsigned C3 = cvt_bf16x2(a1B.z, a1B.w);
#pragma unroll
        for (int f = 0; f < 3; f++) {
            int n = gq + 8*f;
            unsigned B0 = hb(pB.x, n) | (hb(pB.y, n) << 16);
            unsigned B1 = hb(pB.z, n) | (hb(pB.w, n) << 16);
            asm volatile(
                "mma.sync.aligned.m16n8k16.row.col.f32.bf16.bf16.f32 "
                "{%0,%1,%2,%3}, {%4,%5,%6,%7}, {%8,%9}, {%0,%1,%2,%3};"
                : "+f"(d[f][0]), "+f"(d[f][1]), "+f"(d[f][2]), "+f"(d[f][3])
                : "r"(C0), "r"(C1), "r"(C2), "r"(C3), "r"(B0), "r"(B1));
        }
    }

    __shared__ float s_cnum[NSEG][NE];
    for (int j = threadIdx.x; j < NSEG*NE; j += blockDim.x) (&s_cnum[0][0])[j] = 0.f;
    __syncthreads();
#pragma unroll
    for (int f = 0; f < 3; f++) {
        int n0 = 8*f + 2*t;
        if (n0 < NSEG) {
            atomicAdd(&s_cnum[n0][gq],     d[f][0]);
            atomicAdd(&s_cnum[n0][gq + 8], d[f][2]);
        }
        if (n0 + 1 < NSEG) {
            atomicAdd(&s_cnum[n0+1][gq],     d[f][1]);
            atomicAdd(&s_cnum[n0+1][gq + 8], d[f][3]);
        }
    }
    __syncthreads();
    for (int j = threadIdx.x; j < NSEG*NE; j += blockDim.x) {
        float v = (&s_cnum[0][0])[j];
        if (v != 0.f) atomicAdd(&g_cnum[b][0][0] + j, v);
    }
}

// ------- ce_dice body: float2 (2 voxels/thread/iter) to fit registers -------
__device__ __forceinline__ void ce_body(const float* __restrict__ logits,
                                        const int* __restrict__ cls,
                                        int b, int bx) {
    const float2* lb = (const float2*)(logits + (size_t)b * NC * NVOX);
    const int2*   cb = (const int2*)(cls + (size_t)b * NVOX);

    float r_nll = 0.f;
    float r_cardp[NC], r_inter[NC];
#pragma unroll
    for (int c = 0; c < NC; c++) { r_cardp[c]=0.f; r_inter[c]=0.f; }

    int stride = CE_X * 256;
    for (int i = bx * 256 + threadIdx.x; i < NVOX/2; i += stride) {
        int2 t2 = cb[i];
        float2 x2[NC];
#pragma unroll
        for (int c = 0; c < NC; c++) x2[c] = lb[(size_t)c * (NVOX/2) + i];
#pragma unroll
        for (int j = 0; j < 2; j++) {
            float xv[NC];
#pragma unroll
            for (int c = 0; c < NC; c++)
                xv[c] = j ? x2[c].y : x2[c].x;
            int t = j ? t2.y : t2.x;

            float m = xv[0];
#pragma unroll
            for (int c = 1; c < NC; c++) m = fmaxf(m, xv[c]);
            float ex[NC]; float s = 0.f;
#pragma unroll
            for (int c = 0; c < NC; c++) { ex[c] = __expf(xv[c] - m); s += ex[c]; }
            float inv = 1.0f / s;
            float lse = m + __logf(s);
#pragma unroll
            for (int c = 0; c < NC; c++) {
                float p = ex[c] * inv;
                r_cardp[c] += p;
                if (t == c) {
                    r_inter[c] += p;
                    r_nll += lse - xv[c];
                }
            }
        }
    }

    __shared__ float s_acc[17];
    if (threadIdx.x < 17) s_acc[threadIdx.x] = 0.f;
    __syncthreads();
    float vals[17];
    vals[0] = r_nll;
#pragma unroll
    for (int c = 0; c < NC; c++) { vals[1+c]=r_cardp[c]; vals[9+c]=r_inter[c]; }
#pragma unroll
    for (int k = 0; k < 17; k++) {
        float v = vals[k];
#pragma unroll
        for (int o = 16; o; o >>= 1) v += __shfl_xor_sync(0xffffffffu, v, o);
        if ((threadIdx.x & 31) == 0) atomicAdd(&s_acc[k], v);
    }
    __syncthreads();
    int t = threadIdx.x;
    if (t == 0)       atomicAdd(&g_nll, s_acc[0]);
    else if (t < 9)   atomicAdd(&g_cardp[b][t-1], s_acc[t]);
    else if (t < 17)  atomicAdd(&g_inter[b][t-9], s_acc[t]);
}

// ------- fused main pass: segstat blocks + ce_dice blocks in one launch -----
__global__ void __launch_bounds__(256, 4) fused_main(const float* __restrict__ embed,
                                                     const float* __restrict__ logits,
                                                     const int* __restrict__ cls) {
    int b = blockIdx.y;
    if (blockIdx.x < SEG_X) segstat_body(embed, b, blockIdx.x);
    else                    ce_body(logits, cls, b, blockIdx.x - SEG_X);
}

// ------- pull (centers per block) + last-block final fold -------
__global__ void __launch_bounds__(256, 2) pull_kernel(const float* __restrict__ embed,
                                                      float* __restrict__ out) {
    int b = blockIdx.y;
    __shared__ float sc[NSEG][NE + 1];
    __shared__ float s_pull[NSEG];
    __shared__ int s_isLast;
    for (int j = threadIdx.x; j < NSEG*NE; j += blockDim.x) {
        int k = j / NE, c = j % NE;
        float wsum = g_cnt[b][k] + 9.0f * g_bcnt[b][k];
        sc[k][c] = g_cnum[b][k][c] / (wsum + 1e-8f);
    }
    for (int j = threadIdx.x; j < NSEG; j += blockDim.x) s_pull[j] = 0.f;
    __syncthreads();

    const float4* eb = (const float4*)(embed + (size_t)b * NE * NVOX);
    const int4*   pb = (const int4*)(g_packed + (size_t)b * NVOX);

    int stride = PULL_X * blockDim.x;
    for (int i = blockIdx.x * blockDim.x + threadIdx.x; i < NVOX/4; i += stride) {
        int4 p4 = pb[i];
        float4 e4[NE];
#pragma unroll
        for (int c = 0; c < NE; c++)
            e4[c] = eb[(size_t)c * (NVOX/4) + i];

        int   lv[4]; float wv[4]; float ds[4];
#pragma unroll
        for (int j = 0; j < 4; j++) {
            int p = (j==0) ? p4.x : (j==1) ? p4.y : (j==2) ? p4.z : p4.w;
            lv[j] = p & 0x7fffffff;
            wv[j] = (p < 0) ? 10.f : 1.f;
            ds[j] = 0.f;
        }
#pragma unroll
        for (int c = 0; c < NE; c++) {
#pragma unroll
            for (int j = 0; j < 4; j++) {
                float ev = (j==0) ? e4[c].x : (j==1) ? e4[c].y : (j==2) ? e4[c].z : e4[c].w;
                float dv = ev - sc[lv[j]][c];
                ds[j] += dv * dv;
            }
        }
#pragma unroll
        for (int j = 0; j < 4; j++) {
            float dist = sqrtf(ds[j]);
            float tt = fmaxf(dist - 0.5f, 0.f);
            atomicAdd(&s_pull[lv[j]], tt * tt * wv[j]);
        }
    }
    __syncthreads();
    for (int j = threadIdx.x; j < NSEG; j += blockDim.x)
        if (s_pull[j] != 0.f) atomicAdd(&g_pull[b][j], s_pull[j]);

    // ---- last-block final fold ----
    __threadfence();
    __syncthreads();
    if (threadIdx.x == 0)
        s_isLast = (atomicAdd(&g_done, 1) == PULL_TOTAL - 1) ? 1 : 0;
    __syncthreads();
    if (!s_isLast) return;

    __shared__ float sc2[BATCH][NSEG][NE];
    __shared__ float s_lp[BATCH], s_push[BATCH], s_norm[BATCH], s_val[BATCH];
    for (int j = threadIdx.x; j < BATCH*NSEG*NE; j += 256) {
        int bb = j / (NSEG*NE);
        int k = (j / NE) % NSEG;
        int c = j % NE;
        float wsum = g_cnt[bb][k] + 9.0f * g_bcnt[bb][k];
        sc2[bb][k][c] = g_cnum[bb][k][c] / (wsum + 1e-8f);
    }
    __syncthreads();

    int lane = threadIdx.x & 31;
    int warp = threadIdx.x >> 5;
    if (warp < BATCH) {
        int bb = warp;
        int pres_lane = (lane >= 1 && lane < NSEG) ? (g_cnt[bb][lane] > 0.f ? 1 : 0) : 0;
        unsigned mask = __ballot_sync(0xffffffffu, pres_lane);
        float np = (float)__popc(mask);

        float lp = pres_lane ? g_pull[bb][lane] / fmaxf(g_cnt[bb][lane], 1.f) : 0.f;
#pragma unroll
        for (int o = 16; o; o >>= 1) lp += __shfl_xor_sync(0xffffffffu, lp, o);

        float pacc = 0.f;
        for (int pp = lane; pp < 120; pp += 32) {
            int i = 1, rem = pp;
            while (rem >= (NSEG - 1) - i) { rem -= (NSEG - 1) - i; i++; }
            int jj = i + 1 + rem;
            float dsq = 0.f;
#pragma unroll
            for (int c = 0; c < NE; c++) { float dv = sc2[bb][i][c] - sc2[bb][jj][c]; dsq += dv * dv; }
            float pw = sqrtf(dsq);
            float tt = fmaxf(3.0f - pw, 0.f);
            if (((mask >> i) & 1) && ((mask >> jj) & 1)) pacc += tt * tt;
        }
#pragma unroll
        for (int o = 16; o; o >>= 1) pacc += __shfl_xor_sync(0xffffffffu, pacc, o);

        float nacc = 0.f;
        if (pres_lane) {
            float dsq = 0.f;
#pragma unroll
            for (int c = 0; c < NE; c++) dsq += sc2[bb][lane][c] * sc2[bb][lane][c];
            nacc = sqrtf(dsq);
        }
#pragma unroll
        for (int o = 16; o; o >>= 1) nacc += __shfl_xor_sync(0xffffffffu, nacc, o);

        if (lane == 0) {
            float npairs = np * (np - 1.f) * 0.5f;
            s_lp[bb]   = lp;
            s_push[bb] = (npairs > 0.f) ? pacc / fmaxf(npairs, 1.f) : 0.f;
            s_norm[bb] = (np > 0.f)     ? nacc / fmaxf(np, 1.f)     : 0.f;
            s_val[bb]  = (np > 0.f) ? 1.f : 0.f;
        }
    }
    __syncthreads();

    if (threadIdx.x == 0) {
        float lp_sum = 0.f, push_sum = 0.f, norm_sum = 0.f, val_sum = 0.f;
        for (int bb = 0; bb < BATCH; bb++) {
            lp_sum += s_lp[bb]; push_sum += s_push[bb];
            norm_sum += s_norm[bb]; val_sum += s_val[bb];
        }
        float Nf = (float)NTOT;
        float ce = g_nll / Nf;
        float dsum = 0.f;
        for (int bb = 0; bb < BATCH; bb++)
            for (int c = 0; c < NC; c++)
                dsum += (2.0f * g_inter[bb][c] + 1e-5f) /
                        (g_cardp[bb][c] + g_hist[bb][c] + 1e-5f);
        float dice = 1.0f - dsum / (float)(BATCH * NC);

        float ins = (lp_sum + push_sum + 0.001f * norm_sum) / fmaxf(val_sum, 1.f);
        float sem = ce + dice;
        out[0] = sem + ins;
        out[1] = sem;
        out[2] = ce;
        out[3] = dice;
        out[4] = ins;
    }
    __syncthreads();

    // reset accumulators for the next graph replay
    for (int j = threadIdx.x; j < BATCH*NC; j += 256) {
        (&g_cardp[0][0])[j] = 0.f;
        (&g_inter[0][0])[j] = 0.f;
        (&g_hist[0][0])[j]  = 0.f;
    }
    for (int j = threadIdx.x; j < BATCH*NSEG; j += 256) {
        (&g_cnt[0][0])[j]  = 0.f;
        (&g_bcnt[0][0])[j] = 0.f;
        (&g_pull[0][0])[j] = 0.f;
    }
    for (int j = threadIdx.x; j < BATCH*NSEG*NE; j += 256)
        (&g_cnum[0][0][0])[j] = 0.f;
    if (threadIdx.x == 0) { g_nll = 0.f; g_done = 0; }
}

// ---------------- launch ----------------
extern "C" void kernel_launch(void* const* d_in, const int* in_sizes, int n_in,
                              void* d_out, int out_size) {
    const float* sem = (const float*)d_in[0];
    const float* emb = (const float*)d_in[1];
    const int*   cls = (const int*)d_in[2];
    const int*   lab = (const int*)d_in[3];
    float* out = (float*)d_out;

    prep_kernel<<<NTOT / 256, 256>>>(lab, cls);

    dim3 gf(SEG_X + CE_X, BATCH);
    fused_main<<<gf, 256>>>(emb, sem, cls);

    dim3 g3(PULL_X, BATCH);
    pull_kernel<<<g3, 256>>>(emb, out);
}